// round 17
// baseline (speedup 1.0000x reference)
#include <cuda_runtime.h>
#include <cstdint>

// Problem constants
#define Bc   8
#define Tc   256
#define Uc   64
#define Dc   640
#define Vc   1024
#define K2c  1280
#define MOUT (Bc*Tc*Uc)     // 131072 output rows
#define NIT  (Dc/32)        // 20 k-iterations

// Device scratch: only P now (2 MB)
__device__ __align__(16) float g_P[Bc*Uc*Vc];   // P = ReLU(pred)@Wp^T + b

__device__ __forceinline__ uint32_t f2tf(float x) {
    uint32_t r;
    asm("cvt.rna.tf32.f32 %0, %1;" : "=r"(r) : "f"(x));
    return r;
}
__device__ __forceinline__ uint32_t f2tfr(float x) { return f2tf(fmaxf(x, 0.f)); }
__device__ __forceinline__ void cpa(uint32_t dst, const float* src) {
    asm volatile("cp.async.ca.shared.global [%0], [%1], 16;\n"
                 :: "r"(dst), "l"(src));
}
#define CP_COMMIT() asm volatile("cp.async.commit_group;\n" ::: "memory")
#define CP_WAIT2()  asm volatile("cp.async.wait_group 2;\n" ::: "memory")
#define CP_WAIT0()  asm volatile("cp.async.wait_group 0;\n" ::: "memory")

// ---------------------------------------------------------------------------
// pgemm kernel: 64 blocks ONLY (grid fits in one wave; no transform blocks,
// no smem poisoning). 4-stage cp.async pipeline; relu+tf32 at fragment load.
// Also writes the passthrough length tail.
// ---------------------------------------------------------------------------
struct __align__(16) PrepSmem {
    float As[4][64][36];     // 36 KB  pred staging
    float Bs[4][128][36];    // 72 KB  Wp staging
};

__global__ __launch_bounds__(256) void pgemm_kernel(
    const float* __restrict__ pred,
    const float* __restrict__ W,
    const float* __restrict__ bias,
    float* __restrict__ out,
    const int* __restrict__ slen,
    const int* __restrict__ tlen,
    int writeTail)
{
    extern __shared__ char psm_raw[];
    PrepSmem& psm = *reinterpret_cast<PrepSmem*>(psm_raw);

    const int tid = threadIdx.x;
    const int bn0 = (blockIdx.x & 7) * 128;    // v-cols
    const int bm0 = (blockIdx.x >> 3) * 64;    // rows in [0,512)
    const int warp = tid >> 5;
    const int lane = tid & 31;
    const int g    = lane >> 2;
    const int q    = lane & 3;
    const int lr   = tid >> 3;                 // 0..31
    const int lc   = (tid & 7) * 4;
    const int mg   = warp & 3;                 // 4 m-groups x 16 rows
    const int ng   = warp >> 2;                // 2 n-groups x 64 cols

    if (writeTail && blockIdx.x == 0 && tid < 16) {
        size_t tb = (size_t)MOUT * Vc;
        if (tid < 8) out[tb + tid] = (float)slen[tid];
        else         out[tb + tid] = (float)tlen[tid - 8];
    }

    const uint32_t asB = (uint32_t)__cvta_generic_to_shared(psm.As);
    const uint32_t bsB = (uint32_t)__cvta_generic_to_shared(psm.Bs);
    auto aoff = [](int st, int row, int col) -> uint32_t {
        return (uint32_t)((((st * 64 + row) * 36) + col) * 4);
    };
    auto boff = [](int st, int row, int col) -> uint32_t {
        return (uint32_t)((((st * 128 + row) * 36) + col) * 4);
    };

    auto issuePg = [&](int st, int k0) {
#pragma unroll
        for (int i = 0; i < 2; i++)
            cpa(asB + aoff(st, lr + i * 32, lc),
                &pred[(size_t)(bm0 + lr + i * 32) * Dc + k0 + lc]);
#pragma unroll
        for (int i = 0; i < 4; i++)
            cpa(bsB + boff(st, lr + i * 32, lc),
                &W[(size_t)(bn0 + lr + i * 32) * K2c + Dc + k0 + lc]);
    };

    float c[8][4];
#pragma unroll
    for (int nt = 0; nt < 8; nt++)
#pragma unroll
        for (int r = 0; r < 4; r++) c[nt][r] = 0.f;

    issuePg(0, 0);  CP_COMMIT();
    issuePg(1, 32); CP_COMMIT();

#pragma unroll 1
    for (int it = 0; it < NIT; it++) {
        const int st = it & 3;
        const int nx = it + 2;
        if (nx < NIT) issuePg(nx & 3, nx * 32);
        CP_COMMIT();
        CP_WAIT2();
        __syncthreads();
#pragma unroll
        for (int kk = 0; kk < 4; kk++) {
            uint32_t af[4];
            af[0] = f2tfr(psm.As[st][mg*16 + g    ][kk*8 + q    ]);
            af[1] = f2tfr(psm.As[st][mg*16 + g + 8][kk*8 + q    ]);
            af[2] = f2tfr(psm.As[st][mg*16 + g    ][kk*8 + q + 4]);
            af[3] = f2tfr(psm.As[st][mg*16 + g + 8][kk*8 + q + 4]);
#pragma unroll
            for (int nt = 0; nt < 8; nt++) {
                int n = ng*64 + nt*8 + g;
                uint32_t b0 = f2tf(psm.Bs[st][n][kk*8 + q]);
                uint32_t b1 = f2tf(psm.Bs[st][n][kk*8 + q + 4]);
                asm volatile(
                    "mma.sync.aligned.m16n8k8.row.col.f32.tf32.tf32.f32 "
                    "{%0,%1,%2,%3}, {%4,%5,%6,%7}, {%8,%9}, {%0,%1,%2,%3};\n"
                    : "+f"(c[nt][0]), "+f"(c[nt][1]), "+f"(c[nt][2]), "+f"(c[nt][3])
                    : "r"(af[0]), "r"(af[1]), "r"(af[2]), "r"(af[3]),
                      "r"(b0), "r"(b1));
            }
        }
        __syncthreads();
    }
    CP_WAIT0();

    {
        int row = bm0 + mg * 16 + g;
#pragma unroll
        for (int nt = 0; nt < 8; nt++) {
            int col = bn0 + ng*64 + nt*8 + q*2;
            float b0 = bias[col], b1 = bias[col + 1];
            g_P[(size_t)row * Vc + col]           = c[nt][0] + b0;
            g_P[(size_t)row * Vc + col + 1]       = c[nt][1] + b1;
            g_P[(size_t)(row + 8) * Vc + col]     = c[nt][2] + b0;
            g_P[(size_t)(row + 8) * Vc + col + 1] = c[nt][3] + b1;
        }
    }
}

// 192 KB dynamic shared memory, 1 block/SM. Staging holds RAW fp32.
struct __align__(16) Smem {
    float P[64][128];        // 32 KB  P tile (cp.async from g_P, hidden)
    float E[32][128];        // 16 KB  store-phase slab
    float As[4][128][36];    // 72 KB  raw enc staging, 4-stage ring
    float Bs[4][128][36];    // 72 KB  raw W staging, 4-stage ring
};

// ---------------------------------------------------------------------------
// Main kernel: P tile cp.async (first group, drains under E pipeline) +
// E gemm on RAW enc/W (relu+tf32 at fragment load) + store phase.
// grid (8,16), 512 threads, 1 blk/SM.
// ---------------------------------------------------------------------------
__global__ __launch_bounds__(512, 1) void fused_joiner(
    const float* __restrict__ enc,
    const float* __restrict__ W,
    float4* __restrict__ out)
{
    extern __shared__ char smem_raw[];
    Smem& sm = *reinterpret_cast<Smem*>(smem_raw);

    const int tid  = threadIdx.x;
    const int warp = tid >> 5;
    const int lane = tid & 31;
    const int g    = lane >> 2;
    const int q    = lane & 3;
    const int bn0  = blockIdx.x * 128;
    const int b    = blockIdx.y >> 1;
    const int bt0  = b * Tc + (blockIdx.y & 1) * 128;

    const int lr = tid >> 3;        // 0..63
    const int lc = (tid & 7) * 4;   // 0,4..28

    const uint32_t pB  = (uint32_t)__cvta_generic_to_shared(sm.P);
    const uint32_t asB = (uint32_t)__cvta_generic_to_shared(sm.As);
    const uint32_t bsB = (uint32_t)__cvta_generic_to_shared(sm.Bs);
    auto soff = [](int st, int row, int col) -> uint32_t {
        return (uint32_t)((((st * 128 + row) * 36) + col) * 4);
    };

    // ---- issue P-tile load as the FIRST cp.async group (2048 float4) ----
    {
        const float4* P4 = (const float4*)g_P;
#pragma unroll
        for (int j = 0; j < 4; j++) {
            int idx = tid + j * 512;
            int r = idx >> 5, cq = idx & 31;
            cpa(pB + (uint32_t)((r * 128 + cq * 4) * 4),
                (const float*)(P4 + (size_t)(b * Uc + r) * 256 + blockIdx.x * 32 + cq));
        }
        CP_COMMIT();
    }

    // ===================== Phase E: 128 x 128, raw operands ================
    const int mgE = warp & 3;     // m-tiles {mgE, mgE+4}
    const int ngE = warp >> 2;
    float cE[2][4][4];
#pragma unroll
    for (int mt = 0; mt < 2; mt++)
#pragma unroll
        for (int nt = 0; nt < 4; nt++)
#pragma unroll
            for (int r = 0; r < 4; r++) cE[mt][nt][r] = 0.f;

    {
        auto issueE = [&](int st, int k0) {
            cpa(asB + soff(st, lr, lc),
                &enc[(size_t)(bt0 + lr) * Dc + k0 + lc]);
            cpa(asB + soff(st, lr + 64, lc),
                &enc[(size_t)(bt0 + lr + 64) * Dc + k0 + lc]);
            cpa(bsB + soff(st, lr, lc),
                &W[(size_t)(bn0 + lr) * K2c + k0 + lc]);
            cpa(bsB + soff(st, lr + 64, lc),
                &W[(size_t)(bn0 + lr + 64) * K2c + k0 + lc]);
        };

        issueE(0, 0);  CP_COMMIT();
        issueE(1, 32); CP_COMMIT();

#pragma unroll 1
        for (int it = 0; it < NIT; it++) {
            const int st = it & 3;
            const int nx = it + 2;
            if (nx < NIT) issueE(nx & 3, nx * 32);
            CP_COMMIT();
            CP_WAIT2();            // also retires the P group early (oldest)
            __syncthreads();
#pragma unroll
            for (int kk = 0; kk < 4; kk++) {
                uint32_t af[2][4];
#pragma unroll
                for (int mt = 0; mt < 2; mt++) {
                    int r0 = (mgE + 4*mt) * 16;
                    af[mt][0] = f2tfr(sm.As[st][r0 + g    ][kk*8 + q    ]);
                    af[mt][1] = f2tfr(sm.As[st][r0 + g + 8][kk*8 + q    ]);
                    af[mt][2] = f2tfr(sm.As[st][r0 + g    ][kk*8 + q + 4]);
                    af[mt][3] = f2tfr(sm.As[st][r0 + g + 8][kk*8 + q + 4]);
                }
#pragma unroll
                for (int nt = 0; nt < 4; nt++) {
                    int n = ngE*32 + nt*8 + g;
                    uint32_t b0 = f2tf(sm.Bs[st][n][kk*8 + q]);
                    uint32_t b1 = f2tf(sm.Bs[st][n][kk*8 + q + 4]);
#pragma unroll
                    for (int mt = 0; mt < 2; mt++) {
                        asm volatile(
                            "mma.sync.aligned.m16n8k8.row.col.f32.tf32.tf32.f32 "
                            "{%0,%1,%2,%3}, {%4,%5,%6,%7}, {%8,%9}, {%0,%1,%2,%3};\n"
                            : "+f"(cE[mt][nt][0]), "+f"(cE[mt][nt][1]),
                              "+f"(cE[mt][nt][2]), "+f"(cE[mt][nt][3])
                            : "r"(af[mt][0]), "r"(af[mt][1]), "r"(af[mt][2]), "r"(af[mt][3]),
                              "r"(b0), "r"(b1));
                    }
                }
            }
            __syncthreads();
        }
        CP_WAIT0();
        __syncthreads();
    }

    // ===================== Phase C: expand (4 slabs of 32 t) ===============
    const int vq = lane;
#pragma unroll 1
    for (int s = 0; s < 4; s++) {
#pragma unroll
        for (int mt = 0; mt < 2; mt++) {
            int mtile = mgE + 4 * mt;
            if ((mtile >> 1) == s) {
                int r0 = (mtile & 1) * 16 + g;
#pragma unroll
                for (int nt = 0; nt < 4; nt++) {
                    int col = ngE*32 + nt*8 + q*2;
                    sm.E[r0    ][col    ] = cE[mt][nt][0];
                    sm.E[r0    ][col + 1] = cE[mt][nt][1];
                    sm.E[r0 + 8][col    ] = cE[mt][nt][2];
                    sm.E[r0 + 8][col + 1] = cE[mt][nt][3];
                }
            }
        }
        __syncthreads();

        // warp w stores rows {2w, 2w+1}; per u: 1 LDS + 2 STG.cs
        float4 e0 = ((const float4*)sm.E[warp * 2    ])[vq];
        float4 e1 = ((const float4*)sm.E[warp * 2 + 1])[vq];
        size_t ob0 = (size_t)(bt0 + s * 32 + warp * 2) * (Uc * 256)
                     + blockIdx.x * 32 + vq;
        size_t ob1 = ob0 + (size_t)(Uc * 256);
#pragma unroll 4
        for (int u = 0; u < Uc; u++) {
            float4 p = ((const float4*)sm.P[u])[vq];
            float4 r0, r1;
            r0.x = e0.x + p.x; r0.y = e0.y + p.y; r0.z = e0.z + p.z; r0.w = e0.w + p.w;
            r1.x = e1.x + p.x; r1.y = e1.y + p.y; r1.z = e1.z + p.z; r1.w = e1.w + p.w;
            __stcs(&out[ob0 + (size_t)u * 256], r0);
            __stcs(&out[ob1 + (size_t)u * 256], r1);
        }
        __syncthreads();
    }
}

extern "C" void kernel_launch(void* const* d_in, const int* in_sizes, int n_in,
                              void* d_out, int out_size)
{
    const float* enc  = (const float*)d_in[0];  // [B,T,D]
    const int*   slen = (const int*)  d_in[1];  // [B]
    const float* pred = (const float*)d_in[2];  // [B,U,D]
    const int*   tlen = (const int*)  d_in[3];  // [B]
    const float* W    = (const float*)d_in[4];  // [V, 2D]
    const float* bias = (const float*)d_in[5];  // [V]
    float* out = (float*)d_out;

    int writeTail = (out_size >= (int)((size_t)MOUT * Vc + 16)) ? 1 : 0;

    int prepSmem = (int)sizeof(PrepSmem);
    cudaFuncSetAttribute(pgemm_kernel,
                         cudaFuncAttributeMaxDynamicSharedMemorySize, prepSmem);
    pgemm_kernel<<<64, 256, prepSmem>>>(pred, W, bias, out, slen, tlen, writeTail);

    int smemBytes = (int)sizeof(Smem);
    cudaFuncSetAttribute(fused_joiner,
                         cudaFuncAttributeMaxDynamicSharedMemorySize, smemBytes);
    fused_joiner<<<dim3(Vc / 128, 2 * Bc), 512, smemBytes>>>(
        enc, W, (float4*)out);
}